// round 10
// baseline (speedup 1.0000x reference)
#include <cuda_runtime.h>
#include <cstdint>

#define BB 4
#define QQ 256
#define SS 128
#define CC 256
#define BQ 1024
#define BS 512
#define NTOT 131072
#define C1 256
#define C2 64
#define EPSB 1e-5f
#define GRID1 148
#define NTILES 1024
#define XPA 260     // gemmA A pitch
#define T1 512      // layer1 threads

// ---------------- scratch (static device memory; no allocation) -------------
__device__ float g_Aq[BQ * C1];
__device__ float g_As[BS * C1];
__device__ float g_aspt[BB * C1 * SS];              // As raw, transposed [b][o][s]
__device__ uint32_t g_w0frag[2 * 32 * 32 * 32 * 2]; // W0 tf32 frag
__device__ uint32_t g_w1frag[32 * 2 * 2 * 32 * 4];  // W1 tf32 frag [k8][wc][h][lane][4]
__device__ float g_y1[C2 * NTOT];
__device__ float g_y2[NTOT];
__device__ float g_bstat[BB * C1 * 4];
__device__ float g_sc0[C1], g_sh0[C1];
__device__ float g_st1[2 * C2];
__device__ float g_st2[2];
__device__ unsigned g_bar1, g_bar2;

// ---------------- helpers ----------------------------------------------------
__device__ __forceinline__ uint32_t f2tf(float f) {
    uint32_t r;
    asm("cvt.rna.tf32.f32 %0, %1;" : "=r"(r) : "f"(f));
    return r;
}
__device__ __forceinline__ void mma_tf32(float& c0, float& c1, float& c2, float& c3,
                                         uint32_t a0, uint32_t a1, uint32_t a2, uint32_t a3,
                                         uint32_t b0, uint32_t b1) {
    asm("mma.sync.aligned.m16n8k8.row.col.f32.tf32.tf32.f32 "
        "{%0,%1,%2,%3}, {%4,%5,%6,%7}, {%8,%9}, {%0,%1,%2,%3};"
        : "+f"(c0), "+f"(c1), "+f"(c2), "+f"(c3)
        : "r"(a0), "r"(a1), "r"(a2), "r"(a3), "r"(b0), "r"(b1));
}
__device__ __forceinline__ void gridbar(unsigned* bar) {
    __threadfence();
    __syncthreads();
    if (threadIdx.x == 0) {
        atomicAdd(bar, 1u);
        while (atomicAdd(bar, 0u) < GRID1) __nanosleep(200);
    }
    __syncthreads();
    __threadfence();
}

// ---------------- pack W0/W1 into fragment order + zero accums ---------------
__global__ void k_pack(const float* __restrict__ W0, const float* __restrict__ W1) {
    int bx = blockIdx.x, tid = threadIdx.x;
    if (bx == 0) {
        for (int i = tid; i < BB * C1 * 4; i += 256) g_bstat[i] = 0.f;
        if (tid < 2 * C2) g_st1[tid] = 0.f;
        if (tid < 2) g_st2[tid] = 0.f;
        if (tid == 0) { g_bar1 = 0u; g_bar2 = 0u; }
    }
    if (bx < 64) {
        int base = bx * 2048;
#pragma unroll
        for (int it = 0; it < 8; it++) {
            int e = base + it * 256 + tid;
            int reg = e & 1, l = (e >> 1) & 31, ntg = (e >> 6) & 31;
            int k8 = (e >> 11) & 31, h = e >> 16;
            int m = ntg * 8 + (l >> 2);
            int o = k8 * 8 + (l & 3) + 4 * reg;
            g_w0frag[e] = f2tf(W0[m * (2 * CC) + h * CC + o]);
        }
    } else {
        int base = (bx - 64) * 2048;
#pragma unroll
        for (int it = 0; it < 8; it++) {
            int e = base + it * 256 + tid;
            int r4 = e & 3, l = (e >> 2) & 31, h = (e >> 7) & 1;
            int wc = (e >> 8) & 1, k8 = e >> 9;
            int nt = 2 * h + (r4 >> 1), reg = r4 & 1;
            int m = (wc * 4 + nt) * 8 + (l >> 2);
            int o = k8 * 8 + (l & 3) + 4 * reg;
            g_w1frag[e] = f2tf(W1[m * C1 + o]);
        }
    }
}

// ---------------- gemmA: Aq/As via tf32 mma, BN0 stats folded ----------------
extern __shared__ uint32_t smA[];
__global__ void __launch_bounds__(256, 1)
k_gemmA(const float* __restrict__ query, const float* __restrict__ support) {
    uint32_t* xs = smA;
    uint32_t* wf = smA + 128 * XPA;
    int tid = threadIdx.x, w = tid >> 5, l = tid & 31;
    int wr = w >> 1, wc = w & 1;
    int ntb = blockIdx.x, tm = blockIdx.y;
    bool isQ = (tm < 8);
    int rowBase = isQ ? tm * 128 : (tm - 8) * 128;
    const float* inp = (isQ ? query : support) + (size_t)rowBase * CC;
    int h = isQ ? 0 : 1;
    int colBase = ntb * 64;
    int b = isQ ? (tm >> 1) : (tm - 8);

    {
        int m0 = tid >> 6, kc = tid & 63;
#pragma unroll 4
        for (int i = 0; i < 32; i++) {
            int m = m0 + i * 4;
            float4 v = *(const float4*)(inp + m * CC + kc * 4);
            uint4 p;
            p.x = f2tf(v.x); p.y = f2tf(v.y); p.z = f2tf(v.z); p.w = f2tf(v.w);
            *(uint4*)&xs[m * XPA + kc * 4] = p;
        }
    }
    {
        const uint2* src = (const uint2*)g_w0frag;
        uint2* dst = (uint2*)wf;
#pragma unroll 4
        for (int it = 0; it < 32; it++) {
            int j = it * 256 + tid;
            int k8 = j >> 8, ntl = (j >> 5) & 7, ll = j & 31;
            dst[j] = src[((h * 32 + k8) * 32 + ntb * 8 + ntl) * 32 + ll];
        }
    }
    __syncthreads();

    float acc[2][4][4];
#pragma unroll
    for (int mi = 0; mi < 2; mi++)
#pragma unroll
        for (int nt = 0; nt < 4; nt++)
#pragma unroll
            for (int c = 0; c < 4; c++) acc[mi][nt][c] = 0.f;

    int sA = wr * 32 + (l >> 2), oA = l & 3;
#pragma unroll 2
    for (int k8 = 0; k8 < 32; k8++) {
        int ob = k8 * 8 + oA;
        uint32_t a[2][4];
#pragma unroll
        for (int mi = 0; mi < 2; mi++) {
            int s0 = sA + mi * 16;
            a[mi][0] = xs[s0 * XPA + ob];
            a[mi][1] = xs[(s0 + 8) * XPA + ob];
            a[mi][2] = xs[s0 * XPA + ob + 4];
            a[mi][3] = xs[(s0 + 8) * XPA + ob + 4];
        }
#pragma unroll
        for (int nt = 0; nt < 4; nt++) {
            uint2 bb = *(const uint2*)&wf[((k8 * 8 + wc * 4 + nt) * 32 + l) * 2];
#pragma unroll
            for (int mi = 0; mi < 2; mi++)
                mma_tf32(acc[mi][nt][0], acc[mi][nt][1], acc[mi][nt][2], acc[mi][nt][3],
                         a[mi][0], a[mi][1], a[mi][2], a[mi][3], bb.x, bb.y);
        }
    }

    float* dst = isQ ? g_Aq : g_As;
    int qs = isQ ? 0 : 2;
#pragma unroll
    for (int nt = 0; nt < 4; nt++) {
        int m0 = colBase + wc * 32 + nt * 8 + 2 * (l & 3);
        float sum0 = 0.f, sum1 = 0.f, sq0 = 0.f, sq1 = 0.f;
#pragma unroll
        for (int mi = 0; mi < 2; mi++) {
            int s = wr * 32 + (l >> 2) + mi * 16;
            float c0 = acc[mi][nt][0], c1 = acc[mi][nt][1];
            float c2 = acc[mi][nt][2], c3 = acc[mi][nt][3];
            *(float2*)&dst[(rowBase + s) * C1 + m0] = make_float2(c0, c1);
            *(float2*)&dst[(rowBase + s + 8) * C1 + m0] = make_float2(c2, c3);
            sum0 += c0 + c2; sq0 += c0 * c0 + c2 * c2;
            sum1 += c1 + c3; sq1 += c1 * c1 + c3 * c3;
        }
#pragma unroll
        for (int d = 4; d <= 16; d <<= 1) {
            sum0 += __shfl_xor_sync(0xffffffffu, sum0, d);
            sum1 += __shfl_xor_sync(0xffffffffu, sum1, d);
            sq0 += __shfl_xor_sync(0xffffffffu, sq0, d);
            sq1 += __shfl_xor_sync(0xffffffffu, sq1, d);
        }
        if (l < 4) {
            int o = colBase + wc * 32 + nt * 8 + 2 * l;
            atomicAdd(&g_bstat[(b * C1 + o) * 4 + qs], sum0);
            atomicAdd(&g_bstat[(b * C1 + o) * 4 + qs + 1], sq0);
            atomicAdd(&g_bstat[(b * C1 + o + 1) * 4 + qs], sum1);
            atomicAdd(&g_bstat[(b * C1 + o + 1) * 4 + qs + 1], sq1);
        }
    }
}

// ---------------- mid: As transpose + BN0 finalize ---------------------------
__global__ void k_mid(const float* __restrict__ g0, const float* __restrict__ bt0) {
    int bx = blockIdx.x, tid = threadIdx.x;
    if (bx < 128) {
        __shared__ float tsh[32][33];
        int b = bx >> 5, rem = bx & 31;
        int o0 = (rem >> 2) * 32, s0 = (rem & 3) * 32;
        int wr = tid >> 5, c = tid & 31;
#pragma unroll
        for (int i = 0; i < 4; i++) {
            int r = wr + i * 8;
            tsh[r][c] = g_As[(b * SS + s0 + r) * C1 + o0 + c];
        }
        __syncthreads();
#pragma unroll
        for (int i = 0; i < 4; i++) {
            int r = wr + i * 8;
            g_aspt[(b * C1 + o0 + r) * SS + s0 + c] = tsh[c][r];
        }
    } else {
        int o = tid;
        float mAA = 0.f, E2 = 0.f;
#pragma unroll
        for (int b = 0; b < BB; b++) {
            const float* p = &g_bstat[(b * C1 + o) * 4];
            float mq = p[0] * (1.f / QQ);
            float ms = p[2] * (1.f / SS);
            mAA += mq + ms;
            E2 += p[1] * (1.f / QQ) + 2.f * mq * ms + p[3] * (1.f / SS);
        }
        mAA *= (1.f / BB);
        E2 *= (1.f / BB);
        float var = E2 - mAA * mAA;
        float sc = g0[o] * rsqrtf(var + EPSB);
        g_sc0[o] = sc;
        g_sh0[o] = bt0[o] - mAA * sc;   // conv bias b0 cancels exactly
    }
}

// ---------------- layer 1 + fused tail: frag-order X, direct-STG epilogue ----
// X smem layout: 256 blocks (k8, mt) x 32 chunks x 16B, chunk swizzle c^((c&16)>>2).
// A-frag load = one LDS.128; gen STS.128 conflict-free per 8-lane phase.
extern __shared__ uint32_t sm1[];
__global__ void __launch_bounds__(T1, 1)
k_layer1(const float* __restrict__ g1, const float* __restrict__ bt1,
         const float* __restrict__ W2, const float* __restrict__ g2,
         const float* __restrict__ bt2, float* __restrict__ out) {
    uint32_t* xs = sm1;                    // 32768 words: frag-order X
    uint32_t* wf = sm1 + 32768;            // 16384 words: W1 frags
    int tid = threadIdx.x, w = tid >> 5, l = tid & 31;
    int wr = w >> 1, wc = w & 1;           // wr: s-chunk (mtile) 0..7, wc: m-half

    {   // stage W1 fragments once
        const uint4* src = (const uint4*)g_w1frag;
        uint4* dst = (uint4*)wf;
#pragma unroll
        for (int i = 0; i < 8; i++) dst[i * T1 + tid] = src[i * T1 + tid];
    }
    const uint4* wf4 = (const uint4*)wf;
    int lsw = l ^ ((l & 16) >> 2);         // swizzled chunk for A-load

    // gen mapping: thread owns o-pair (o, o+4), o = k8g*8 + olg
    int k8g = tid >> 4;
    int rg = tid & 15;
    int olg = rg & 3;
    int ug = rg >> 2;                      // 0..3
    int slb = (ug & 1) * 4;
    int mtb = ug >> 1;                     // 0 or 1
    int og = k8g * 8 + olg;
    float scA = g_sc0[og], shA = g_sh0[og];
    float scB = g_sc0[og + 4], shB = g_sh0[og + 4];

    __syncthreads();   // wf visible (also covered by in-loop sync)

    for (int t = blockIdx.x; t < NTILES; t += GRID1) {
        int b = t >> 8;

        {   // ---- gen X into frag-order smem ----
            float aqA = fmaf(g_Aq[t * C1 + og], scA, shA);
            float aqB = fmaf(g_Aq[t * C1 + og + 4], scB, shB);
            const float4* rowA = (const float4*)(g_aspt + (size_t)(b * C1 + og) * SS);
            const float4* rowB = (const float4*)(g_aspt + (size_t)(b * C1 + og + 4) * SS);
#pragma unroll
            for (int i = 0; i < 4; i++) {
                int mt = mtb + 2 * i;
                int b4 = mt * 4 + (slb >> 2);
                float4 vAlo = rowA[b4], vAhi = rowA[b4 + 2];
                float4 vBlo = rowB[b4], vBhi = rowB[b4 + 2];
                uint32_t* blk = &xs[(k8g * 8 + mt) * 128];
#pragma unroll
                for (int j = 0; j < 4; j++) {
                    int sl = slb + j;
                    int c = sl * 4 + olg;
                    int cp = c ^ ((c & 16) >> 2);
                    float a_lo = (j == 0) ? vAlo.x : (j == 1) ? vAlo.y : (j == 2) ? vAlo.z : vAlo.w;
                    float a_hi = (j == 0) ? vAhi.x : (j == 1) ? vAhi.y : (j == 2) ? vAhi.z : vAhi.w;
                    float b_lo = (j == 0) ? vBlo.x : (j == 1) ? vBlo.y : (j == 2) ? vBlo.z : vBlo.w;
                    float b_hi = (j == 0) ? vBhi.x : (j == 1) ? vBhi.y : (j == 2) ? vBhi.z : vBhi.w;
                    uint4 p;
                    p.x = f2tf(fmaxf(fmaf(a_lo, scA, aqA), 0.f));
                    p.y = f2tf(fmaxf(fmaf(a_hi, scA, aqA), 0.f));
                    p.z = f2tf(fmaxf(fmaf(b_lo, scB, aqB), 0.f));
                    p.w = f2tf(fmaxf(fmaf(b_hi, scB, aqB), 0.f));
                    *(uint4*)&blk[cp * 4] = p;
                }
            }
        }
        __syncthreads();

        // ---- MMA: full K with register double-buffer ----
        float acc[4][4];
#pragma unroll
        for (int nt = 0; nt < 4; nt++)
#pragma unroll
            for (int c = 0; c < 4; c++) acc[nt][c] = 0.f;

        uint4 aC = *(const uint4*)&xs[(0 * 8 + wr) * 128 + lsw * 4];
        uint4 bC0 = wf4[wc * 64 + l];
        uint4 bC1 = wf4[wc * 64 + 32 + l];
#pragma unroll
        for (int k8 = 0; k8 < 32; k8++) {
            uint4 aN, bN0, bN1;
            if (k8 < 31) {
                aN = *(const uint4*)&xs[((k8 + 1) * 8 + wr) * 128 + lsw * 4];
                bN0 = wf4[(k8 + 1) * 128 + wc * 64 + l];
                bN1 = wf4[(k8 + 1) * 128 + wc * 64 + 32 + l];
            }
            mma_tf32(acc[0][0], acc[0][1], acc[0][2], acc[0][3],
                     aC.x, aC.y, aC.z, aC.w, bC0.x, bC0.y);
            mma_tf32(acc[1][0], acc[1][1], acc[1][2], acc[1][3],
                     aC.x, aC.y, aC.z, aC.w, bC0.z, bC0.w);
            mma_tf32(acc[2][0], acc[2][1], acc[2][2], acc[2][3],
                     aC.x, aC.y, aC.z, aC.w, bC1.x, bC1.y);
            mma_tf32(acc[3][0], acc[3][1], acc[3][2], acc[3][3],
                     aC.x, aC.y, aC.z, aC.w, bC1.z, bC1.w);
            if (k8 < 31) { aC = aN; bC0 = bN0; bC1 = bN1; }
        }
        __syncthreads();   // all xs reads done; next gen may overwrite

        {   // ---- epilogue: direct STG + butterfly BN1 stats (regs/global only) ----
            int sL = wr * 16 + (l >> 2);
            float* yb = g_y1 + (size_t)t * 128;
#pragma unroll
            for (int nt = 0; nt < 4; nt++) {
                int m0 = wc * 32 + nt * 8 + 2 * (l & 3);
                float c0 = acc[nt][0], c1 = acc[nt][1];
                float c2 = acc[nt][2], c3 = acc[nt][3];
                yb[(size_t)m0 * NTOT + sL] = c0;
                yb[(size_t)(m0 + 1) * NTOT + sL] = c1;
                yb[(size_t)m0 * NTOT + sL + 8] = c2;
                yb[(size_t)(m0 + 1) * NTOT + sL + 8] = c3;
                float sE = c0 + c2, sO = c1 + c3;
                float qE = c0 * c0 + c2 * c2, qO = c1 * c1 + c3 * c3;
#pragma unroll
                for (int d = 4; d <= 16; d <<= 1) {
                    sE += __shfl_xor_sync(0xffffffffu, sE, d);
                    sO += __shfl_xor_sync(0xffffffffu, sO, d);
                    qE += __shfl_xor_sync(0xffffffffu, qE, d);
                    qO += __shfl_xor_sync(0xffffffffu, qO, d);
                }
                if ((l >> 2) == 0) {
                    atomicAdd(&g_st1[m0], sE);
                    atomicAdd(&g_st1[C2 + m0], qE);
                    atomicAdd(&g_st1[m0 + 1], sO);
                    atomicAdd(&g_st1[C2 + m0 + 1], qO);
                }
            }
        }
    }

    // ---------------- fused tail ----------------
    gridbar(&g_bar1);

    float* sc1s = (float*)sm1;
    float* sh1s = sc1s + C2;
    float* w2s = sh1s + C2;
    if (tid < C2) {
        float mean = g_st1[tid] * (1.f / NTOT);
        float var = g_st1[C2 + tid] * (1.f / NTOT) - mean * mean;
        float sc = g1[tid] * rsqrtf(var + EPSB);
        sc1s[tid] = sc;
        sh1s[tid] = bt1[tid] - mean * sc;  // conv bias b1 cancels exactly
        w2s[tid] = W2[tid];
    }
    __syncthreads();

    int idx = blockIdx.x * T1 + tid;
    if (idx < NTOT / 4) {
        const float4* y14 = (const float4*)g_y1;
        float4 acc = make_float4(0.f, 0.f, 0.f, 0.f);
#pragma unroll 8
        for (int m = 0; m < C2; m++) {
            float4 v = y14[(size_t)m * (NTOT / 4) + idx];
            float scm = sc1s[m], shm = sh1s[m], wm = w2s[m];
            acc.x = fmaf(fmaxf(fmaf(v.x, scm, shm), 0.f), wm, acc.x);
            acc.y = fmaf(fmaxf(fmaf(v.y, scm, shm), 0.f), wm, acc.y);
            acc.z = fmaf(fmaxf(fmaf(v.z, scm, shm), 0.f), wm, acc.z);
            acc.w = fmaf(fmaxf(fmaf(v.w, scm, shm), 0.f), wm, acc.w);
        }
        ((float4*)g_y2)[idx] = acc;   // b2 cancels exactly
        float s1 = acc.x + acc.y + acc.z + acc.w;
        float s2 = acc.x * acc.x + acc.y * acc.y + acc.z * acc.z + acc.w * acc.w;
#pragma unroll
        for (int d = 16; d > 0; d >>= 1) {
            s1 += __shfl_xor_sync(0xffffffffu, s1, d);
            s2 += __shfl_xor_sync(0xffffffffu, s2, d);
        }
        if (l == 0) {
            atomicAdd(&g_st2[0], s1);
            atomicAdd(&g_st2[1], s2);
        }
    }

    gridbar(&g_bar2);

    if (idx < NTOT / 4) {
        float mean = g_st2[0] * (1.f / NTOT);
        float var = g_st2[1] * (1.f / NTOT) - mean * mean;
        float sc = g2[0] * rsqrtf(var + EPSB);
        float sh = bt2[0] - mean * sc;   // conv bias b2 cancels exactly
        float4 v = ((const float4*)g_y2)[idx];
        float4 r;
        r.x = fmaxf(fmaf(v.x, sc, sh), 0.f);
        r.y = fmaxf(fmaf(v.y, sc, sh), 0.f);
        r.z = fmaxf(fmaf(v.z, sc, sh), 0.f);
        r.w = fmaxf(fmaf(v.w, sc, sh), 0.f);
        ((float4*)out)[idx] = r;
    }
}

// ---------------- launch ------------------------------------------------------
extern "C" void kernel_launch(void* const* d_in, const int* in_sizes, int n_in,
                              void* d_out, int out_size) {
    (void)in_sizes; (void)n_in; (void)out_size;
    const float* support = (const float*)d_in[0];
    const float* query   = (const float*)d_in[1];
    const float* W0  = (const float*)d_in[2];
    // b0, b1, b2 cancel exactly against training-mode BN means; unused.
    const float* g0  = (const float*)d_in[4];
    const float* bt0 = (const float*)d_in[5];
    const float* W1  = (const float*)d_in[6];
    const float* g1  = (const float*)d_in[8];
    const float* bt1 = (const float*)d_in[9];
    const float* W2  = (const float*)d_in[10];
    const float* g2  = (const float*)d_in[12];
    const float* bt2 = (const float*)d_in[13];
    float* out = (float*)d_out;

    size_t smemA = (size_t)(128 * XPA + 16384) * 4;   // 198656 B
    size_t smem1 = (size_t)(32768 + 16384) * 4;       // 196608 B
    cudaFuncSetAttribute(k_gemmA, cudaFuncAttributeMaxDynamicSharedMemorySize, (int)smemA);
    cudaFuncSetAttribute(k_layer1, cudaFuncAttributeMaxDynamicSharedMemorySize, (int)smem1);

    k_pack<<<72, 256>>>(W0, W1);
    dim3 gA(4, 12);
    k_gemmA<<<gA, 256, smemA>>>(query, support);
    k_mid<<<129, 256>>>(g0, bt0);
    k_layer1<<<GRID1, T1, smem1>>>(g1, bt1, W2, g2, bt2, out);
}

// round 11
// speedup vs baseline: 1.4962x; 1.4962x over previous
#include <cuda_runtime.h>
#include <cstdint>

#define BB 4
#define QQ 256
#define SS 128
#define CC 256
#define BQ 1024
#define BS 512
#define NTOT 131072
#define C1 256
#define C2 64
#define EPSB 1e-5f
#define GRID1 148
#define NTILES 1024
#define XPA 260     // gemmA A pitch
#define DPITCH 132  // D staging pitch
#define T1 512      // layer1 threads

// ---------------- scratch (static device memory; no allocation) -------------
__device__ float g_Aq[BQ * C1];
__device__ float g_As[BS * C1];
__device__ float g_aspt[BB * C1 * SS];              // As raw, transposed [b][o][s]
__device__ uint32_t g_w0frag[2 * 32 * 32 * 32 * 2]; // W0 tf32 frag
__device__ uint32_t g_w1frag[32 * 2 * 2 * 32 * 4];  // W1 tf32 frag [k8][wc][h][lane][4]
__device__ float g_y1[C2 * NTOT];
__device__ float g_y2[NTOT];
__device__ float g_bstat[BB * C1 * 4];
__device__ float g_sc0[C1], g_sh0[C1];
__device__ float g_st1[2 * C2];
__device__ float g_st2[2];
__device__ unsigned g_bar1, g_bar2;

// ---------------- helpers ----------------------------------------------------
__device__ __forceinline__ uint32_t f2tf(float f) {
    uint32_t r;
    asm("cvt.rna.tf32.f32 %0, %1;" : "=r"(r) : "f"(f));
    return r;
}
__device__ __forceinline__ void mma_tf32(float& c0, float& c1, float& c2, float& c3,
                                         uint32_t a0, uint32_t a1, uint32_t a2, uint32_t a3,
                                         uint32_t b0, uint32_t b1) {
    asm("mma.sync.aligned.m16n8k8.row.col.f32.tf32.tf32.f32 "
        "{%0,%1,%2,%3}, {%4,%5,%6,%7}, {%8,%9}, {%0,%1,%2,%3};"
        : "+f"(c0), "+f"(c1), "+f"(c2), "+f"(c3)
        : "r"(a0), "r"(a1), "r"(a2), "r"(a3), "r"(b0), "r"(b1));
}
__device__ __forceinline__ void gridbar(unsigned* bar) {
    __threadfence();
    __syncthreads();
    if (threadIdx.x == 0) {
        atomicAdd(bar, 1u);
        while (atomicAdd(bar, 0u) < GRID1) __nanosleep(200);
    }
    __syncthreads();
    __threadfence();
}

// ---------------- pack W0/W1 into fragment order + zero accums ---------------
__global__ void k_pack(const float* __restrict__ W0, const float* __restrict__ W1) {
    int bx = blockIdx.x, tid = threadIdx.x;
    if (bx == 0) {
        for (int i = tid; i < BB * C1 * 4; i += 256) g_bstat[i] = 0.f;
        if (tid < 2 * C2) g_st1[tid] = 0.f;
        if (tid < 2) g_st2[tid] = 0.f;
        if (tid == 0) { g_bar1 = 0u; g_bar2 = 0u; }
    }
    if (bx < 64) {
        int base = bx * 2048;
#pragma unroll
        for (int it = 0; it < 8; it++) {
            int e = base + it * 256 + tid;
            int reg = e & 1, l = (e >> 1) & 31, ntg = (e >> 6) & 31;
            int k8 = (e >> 11) & 31, h = e >> 16;
            int m = ntg * 8 + (l >> 2);
            int o = k8 * 8 + (l & 3) + 4 * reg;
            g_w0frag[e] = f2tf(W0[m * (2 * CC) + h * CC + o]);
        }
    } else {
        int base = (bx - 64) * 2048;
#pragma unroll
        for (int it = 0; it < 8; it++) {
            int e = base + it * 256 + tid;
            int r4 = e & 3, l = (e >> 2) & 31, h = (e >> 7) & 1;
            int wc = (e >> 8) & 1, k8 = e >> 9;
            int nt = 2 * h + (r4 >> 1), reg = r4 & 1;
            int m = (wc * 4 + nt) * 8 + (l >> 2);
            int o = k8 * 8 + (l & 3) + 4 * reg;
            g_w1frag[e] = f2tf(W1[m * C1 + o]);
        }
    }
}

// ---------------- gemmA: Aq/As via tf32 mma, BN0 stats folded ----------------
extern __shared__ uint32_t smA[];
__global__ void __launch_bounds__(256, 1)
k_gemmA(const float* __restrict__ query, const float* __restrict__ support) {
    uint32_t* xs = smA;
    uint32_t* wf = smA + 128 * XPA;
    int tid = threadIdx.x, w = tid >> 5, l = tid & 31;
    int wr = w >> 1, wc = w & 1;
    int ntb = blockIdx.x, tm = blockIdx.y;
    bool isQ = (tm < 8);
    int rowBase = isQ ? tm * 128 : (tm - 8) * 128;
    const float* inp = (isQ ? query : support) + (size_t)rowBase * CC;
    int h = isQ ? 0 : 1;
    int colBase = ntb * 64;
    int b = isQ ? (tm >> 1) : (tm - 8);

    {
        int m0 = tid >> 6, kc = tid & 63;
#pragma unroll 4
        for (int i = 0; i < 32; i++) {
            int m = m0 + i * 4;
            float4 v = *(const float4*)(inp + m * CC + kc * 4);
            uint4 p;
            p.x = f2tf(v.x); p.y = f2tf(v.y); p.z = f2tf(v.z); p.w = f2tf(v.w);
            *(uint4*)&xs[m * XPA + kc * 4] = p;
        }
    }
    {
        const uint2* src = (const uint2*)g_w0frag;
        uint2* dst = (uint2*)wf;
#pragma unroll 4
        for (int it = 0; it < 32; it++) {
            int j = it * 256 + tid;
            int k8 = j >> 8, ntl = (j >> 5) & 7, ll = j & 31;
            dst[j] = src[((h * 32 + k8) * 32 + ntb * 8 + ntl) * 32 + ll];
        }
    }
    __syncthreads();

    float acc[2][4][4];
#pragma unroll
    for (int mi = 0; mi < 2; mi++)
#pragma unroll
        for (int nt = 0; nt < 4; nt++)
#pragma unroll
            for (int c = 0; c < 4; c++) acc[mi][nt][c] = 0.f;

    int sA = wr * 32 + (l >> 2), oA = l & 3;
#pragma unroll 2
    for (int k8 = 0; k8 < 32; k8++) {
        int ob = k8 * 8 + oA;
        uint32_t a[2][4];
#pragma unroll
        for (int mi = 0; mi < 2; mi++) {
            int s0 = sA + mi * 16;
            a[mi][0] = xs[s0 * XPA + ob];
            a[mi][1] = xs[(s0 + 8) * XPA + ob];
            a[mi][2] = xs[s0 * XPA + ob + 4];
            a[mi][3] = xs[(s0 + 8) * XPA + ob + 4];
        }
#pragma unroll
        for (int nt = 0; nt < 4; nt++) {
            uint2 bb = *(const uint2*)&wf[((k8 * 8 + wc * 4 + nt) * 32 + l) * 2];
#pragma unroll
            for (int mi = 0; mi < 2; mi++)
                mma_tf32(acc[mi][nt][0], acc[mi][nt][1], acc[mi][nt][2], acc[mi][nt][3],
                         a[mi][0], a[mi][1], a[mi][2], a[mi][3], bb.x, bb.y);
        }
    }

    float* dst = isQ ? g_Aq : g_As;
    int qs = isQ ? 0 : 2;
#pragma unroll
    for (int nt = 0; nt < 4; nt++) {
        int m0 = colBase + wc * 32 + nt * 8 + 2 * (l & 3);
        float sum0 = 0.f, sum1 = 0.f, sq0 = 0.f, sq1 = 0.f;
#pragma unroll
        for (int mi = 0; mi < 2; mi++) {
            int s = wr * 32 + (l >> 2) + mi * 16;
            float c0 = acc[mi][nt][0], c1 = acc[mi][nt][1];
            float c2 = acc[mi][nt][2], c3 = acc[mi][nt][3];
            *(float2*)&dst[(rowBase + s) * C1 + m0] = make_float2(c0, c1);
            *(float2*)&dst[(rowBase + s + 8) * C1 + m0] = make_float2(c2, c3);
            sum0 += c0 + c2; sq0 += c0 * c0 + c2 * c2;
            sum1 += c1 + c3; sq1 += c1 * c1 + c3 * c3;
        }
#pragma unroll
        for (int d = 4; d <= 16; d <<= 1) {
            sum0 += __shfl_xor_sync(0xffffffffu, sum0, d);
            sum1 += __shfl_xor_sync(0xffffffffu, sum1, d);
            sq0 += __shfl_xor_sync(0xffffffffu, sq0, d);
            sq1 += __shfl_xor_sync(0xffffffffu, sq1, d);
        }
        if (l < 4) {
            int o = colBase + wc * 32 + nt * 8 + 2 * l;
            atomicAdd(&g_bstat[(b * C1 + o) * 4 + qs], sum0);
            atomicAdd(&g_bstat[(b * C1 + o) * 4 + qs + 1], sq0);
            atomicAdd(&g_bstat[(b * C1 + o + 1) * 4 + qs], sum1);
            atomicAdd(&g_bstat[(b * C1 + o + 1) * 4 + qs + 1], sq1);
        }
    }
}

// ---------------- mid: As transpose + BN0 finalize ---------------------------
__global__ void k_mid(const float* __restrict__ g0, const float* __restrict__ bt0) {
    int bx = blockIdx.x, tid = threadIdx.x;
    if (bx < 128) {
        __shared__ float tsh[32][33];
        int b = bx >> 5, rem = bx & 31;
        int o0 = (rem >> 2) * 32, s0 = (rem & 3) * 32;
        int wr = tid >> 5, c = tid & 31;
#pragma unroll
        for (int i = 0; i < 4; i++) {
            int r = wr + i * 8;
            tsh[r][c] = g_As[(b * SS + s0 + r) * C1 + o0 + c];
        }
        __syncthreads();
#pragma unroll
        for (int i = 0; i < 4; i++) {
            int r = wr + i * 8;
            g_aspt[(b * C1 + o0 + r) * SS + s0 + c] = tsh[c][r];
        }
    } else {
        int o = tid;
        float mAA = 0.f, E2 = 0.f;
#pragma unroll
        for (int b = 0; b < BB; b++) {
            const float* p = &g_bstat[(b * C1 + o) * 4];
            float mq = p[0] * (1.f / QQ);
            float ms = p[2] * (1.f / SS);
            mAA += mq + ms;
            E2 += p[1] * (1.f / QQ) + 2.f * mq * ms + p[3] * (1.f / SS);
        }
        mAA *= (1.f / BB);
        E2 *= (1.f / BB);
        float var = E2 - mAA * mAA;
        float sc = g0[o] * rsqrtf(var + EPSB);
        g_sc0[o] = sc;
        g_sh0[o] = bt0[o] - mAA * sc;   // conv bias b0 cancels exactly
    }
}

// ---------------- layer 1 + fused tail: frag-order X, staged epilogue --------
// X smem: 256 blocks (k8, mt) x 32 chunks x 16B, chunk swizzle c^((c&16)>>2).
// A-frag load = one LDS.128; epilogue staged in smem for coalesced copy-out.
extern __shared__ uint32_t sm1[];
__global__ void __launch_bounds__(T1, 1)
k_layer1(const float* __restrict__ g1, const float* __restrict__ bt1,
         const float* __restrict__ W2, const float* __restrict__ g2,
         const float* __restrict__ bt2, float* __restrict__ out) {
    uint32_t* xs = sm1;                    // 32768 words: frag-order X / D overlay
    uint32_t* wf = sm1 + 32768;            // 16384 words: W1 frags
    float* xsf = (float*)sm1;              // D staging overlay
    int tid = threadIdx.x, w = tid >> 5, l = tid & 31;
    int wr = w >> 1, wc = w & 1;           // wr: s-chunk (mtile) 0..7, wc: m-half

    {   // stage W1 fragments once
        const uint4* src = (const uint4*)g_w1frag;
        uint4* dst = (uint4*)wf;
#pragma unroll
        for (int i = 0; i < 8; i++) dst[i * T1 + tid] = src[i * T1 + tid];
    }
    const uint4* wf4 = (const uint4*)wf;
    int lsw = l ^ ((l & 16) >> 2);         // swizzled chunk for A-load

    // gen mapping: thread owns o-pair (o, o+4), o = k8g*8 + olg
    int k8g = tid >> 4;
    int rg = tid & 15;
    int olg = rg & 3;
    int ug = rg >> 2;                      // 0..3
    int slb = (ug & 1) * 4;
    int mtb = ug >> 1;                     // 0 or 1
    int og = k8g * 8 + olg;
    float scA = g_sc0[og], shA = g_sh0[og];
    float scB = g_sc0[og + 4], shB = g_sh0[og + 4];

    __syncthreads();   // wf visible

    for (int t = blockIdx.x; t < NTILES; t += GRID1) {
        int b = t >> 8;

        {   // ---- gen X into frag-order smem ----
            float aqA = fmaf(g_Aq[t * C1 + og], scA, shA);
            float aqB = fmaf(g_Aq[t * C1 + og + 4], scB, shB);
            const float4* rowA = (const float4*)(g_aspt + (size_t)(b * C1 + og) * SS);
            const float4* rowB = (const float4*)(g_aspt + (size_t)(b * C1 + og + 4) * SS);
#pragma unroll
            for (int i = 0; i < 4; i++) {
                int mt = mtb + 2 * i;
                int b4 = mt * 4 + (slb >> 2);
                float4 vAlo = rowA[b4], vAhi = rowA[b4 + 2];
                float4 vBlo = rowB[b4], vBhi = rowB[b4 + 2];
                uint32_t* blk = &xs[(k8g * 8 + mt) * 128];
#pragma unroll
                for (int j = 0; j < 4; j++) {
                    int sl = slb + j;
                    int c = sl * 4 + olg;
                    int cp = c ^ ((c & 16) >> 2);
                    float a_lo = (j == 0) ? vAlo.x : (j == 1) ? vAlo.y : (j == 2) ? vAlo.z : vAlo.w;
                    float a_hi = (j == 0) ? vAhi.x : (j == 1) ? vAhi.y : (j == 2) ? vAhi.z : vAhi.w;
                    float b_lo = (j == 0) ? vBlo.x : (j == 1) ? vBlo.y : (j == 2) ? vBlo.z : vBlo.w;
                    float b_hi = (j == 0) ? vBhi.x : (j == 1) ? vBhi.y : (j == 2) ? vBhi.z : vBhi.w;
                    uint4 p;
                    p.x = f2tf(fmaxf(fmaf(a_lo, scA, aqA), 0.f));
                    p.y = f2tf(fmaxf(fmaf(a_hi, scA, aqA), 0.f));
                    p.z = f2tf(fmaxf(fmaf(b_lo, scB, aqB), 0.f));
                    p.w = f2tf(fmaxf(fmaf(b_hi, scB, aqB), 0.f));
                    *(uint4*)&blk[cp * 4] = p;
                }
            }
        }
        __syncthreads();

        // ---- MMA: full K with register double-buffer ----
        float acc[4][4];
#pragma unroll
        for (int nt = 0; nt < 4; nt++)
#pragma unroll
            for (int c = 0; c < 4; c++) acc[nt][c] = 0.f;

        uint4 aC = *(const uint4*)&xs[(0 * 8 + wr) * 128 + lsw * 4];
        uint4 bC0 = wf4[wc * 64 + l];
        uint4 bC1 = wf4[wc * 64 + 32 + l];
#pragma unroll
        for (int k8 = 0; k8 < 32; k8++) {
            uint4 aN, bN0, bN1;
            if (k8 < 31) {
                aN = *(const uint4*)&xs[((k8 + 1) * 8 + wr) * 128 + lsw * 4];
                bN0 = wf4[(k8 + 1) * 128 + wc * 64 + l];
                bN1 = wf4[(k8 + 1) * 128 + wc * 64 + 32 + l];
            }
            mma_tf32(acc[0][0], acc[0][1], acc[0][2], acc[0][3],
                     aC.x, aC.y, aC.z, aC.w, bC0.x, bC0.y);
            mma_tf32(acc[1][0], acc[1][1], acc[1][2], acc[1][3],
                     aC.x, aC.y, aC.z, aC.w, bC0.z, bC0.w);
            mma_tf32(acc[2][0], acc[2][1], acc[2][2], acc[2][3],
                     aC.x, aC.y, aC.z, aC.w, bC1.x, bC1.y);
            mma_tf32(acc[3][0], acc[3][1], acc[3][2], acc[3][3],
                     aC.x, aC.y, aC.z, aC.w, bC1.z, bC1.w);
            if (k8 < 31) { aC = aN; bC0 = bN0; bC1 = bN1; }
        }
        __syncthreads();   // all xs reads done; stage D into overlay

        {   // ---- stage D (coalescing buffer) ----
            int s0e = wr * 16 + (l >> 2);
            int mB = wc * 32 + 2 * (l & 3);
#pragma unroll
            for (int nt = 0; nt < 4; nt++) {
                int m0 = mB + nt * 8;
                xsf[m0 * DPITCH + s0e] = acc[nt][0];
                xsf[(m0 + 1) * DPITCH + s0e] = acc[nt][1];
                xsf[m0 * DPITCH + s0e + 8] = acc[nt][2];
                xsf[(m0 + 1) * DPITCH + s0e + 8] = acc[nt][3];
            }
        }
        __syncthreads();

        {   // ---- coalesced copy-out + BN1 partial sums ----
            float* yb = g_y1 + (size_t)t * 128;
#pragma unroll
            for (int it = 0; it < 4; it++) {
                int m = w + 16 * it;
                float4 v = *(const float4*)&xsf[m * DPITCH + 4 * l];
                *(float4*)(yb + (size_t)m * NTOT + 4 * l) = v;
                float s1 = v.x + v.y + v.z + v.w;
                float s2 = v.x * v.x + v.y * v.y + v.z * v.z + v.w * v.w;
#pragma unroll
                for (int d = 16; d > 0; d >>= 1) {
                    s1 += __shfl_xor_sync(0xffffffffu, s1, d);
                    s2 += __shfl_xor_sync(0xffffffffu, s2, d);
                }
                if (l == 0) {
                    atomicAdd(&g_st1[m], s1);
                    atomicAdd(&g_st1[C2 + m], s2);
                }
            }
        }
        __syncthreads();   // D overlay consumed before next tile's gen
    }

    // ---------------- fused tail ----------------
    gridbar(&g_bar1);

    float* sc1s = (float*)sm1;
    float* sh1s = sc1s + C2;
    float* w2s = sh1s + C2;
    if (tid < C2) {
        float mean = g_st1[tid] * (1.f / NTOT);
        float var = g_st1[C2 + tid] * (1.f / NTOT) - mean * mean;
        float sc = g1[tid] * rsqrtf(var + EPSB);
        sc1s[tid] = sc;
        sh1s[tid] = bt1[tid] - mean * sc;  // conv bias b1 cancels exactly
        w2s[tid] = W2[tid];
    }
    __syncthreads();

    int idx = blockIdx.x * T1 + tid;
    if (idx < NTOT / 4) {
        const float4* y14 = (const float4*)g_y1;
        float4 acc = make_float4(0.f, 0.f, 0.f, 0.f);
#pragma unroll 8
        for (int m = 0; m < C2; m++) {
            float4 v = y14[(size_t)m * (NTOT / 4) + idx];
            float scm = sc1s[m], shm = sh1s[m], wm = w2s[m];
            acc.x = fmaf(fmaxf(fmaf(v.x, scm, shm), 0.f), wm, acc.x);
            acc.y = fmaf(fmaxf(fmaf(v.y, scm, shm), 0.f), wm, acc.y);
            acc.z = fmaf(fmaxf(fmaf(v.z, scm, shm), 0.f), wm, acc.z);
            acc.w = fmaf(fmaxf(fmaf(v.w, scm, shm), 0.f), wm, acc.w);
        }
        ((float4*)g_y2)[idx] = acc;   // b2 cancels exactly
        float s1 = acc.x + acc.y + acc.z + acc.w;
        float s2 = acc.x * acc.x + acc.y * acc.y + acc.z * acc.z + acc.w * acc.w;
#pragma unroll
        for (int d = 16; d > 0; d >>= 1) {
            s1 += __shfl_xor_sync(0xffffffffu, s1, d);
            s2 += __shfl_xor_sync(0xffffffffu, s2, d);
        }
        if (l == 0) {
            atomicAdd(&g_st2[0], s1);
            atomicAdd(&g_st2[1], s2);
        }
    }

    gridbar(&g_bar2);

    if (idx < NTOT / 4) {
        float mean = g_st2[0] * (1.f / NTOT);
        float var = g_st2[1] * (1.f / NTOT) - mean * mean;
        float sc = g2[0] * rsqrtf(var + EPSB);
        float sh = bt2[0] - mean * sc;   // conv bias b2 cancels exactly
        float4 v = ((const float4*)g_y2)[idx];
        float4 r;
        r.x = fmaxf(fmaf(v.x, sc, sh), 0.f);
        r.y = fmaxf(fmaf(v.y, sc, sh), 0.f);
        r.z = fmaxf(fmaf(v.z, sc, sh), 0.f);
        r.w = fmaxf(fmaf(v.w, sc, sh), 0.f);
        ((float4*)out)[idx] = r;
    }
}

// ---------------- launch ------------------------------------------------------
extern "C" void kernel_launch(void* const* d_in, const int* in_sizes, int n_in,
                              void* d_out, int out_size) {
    (void)in_sizes; (void)n_in; (void)out_size;
    const float* support = (const float*)d_in[0];
    const float* query   = (const float*)d_in[1];
    const float* W0  = (const float*)d_in[2];
    // b0, b1, b2 cancel exactly against training-mode BN means; unused.
    const float* g0  = (const float*)d_in[4];
    const float* bt0 = (const float*)d_in[5];
    const float* W1  = (const float*)d_in[6];
    const float* g1  = (const float*)d_in[8];
    const float* bt1 = (const float*)d_in[9];
    const float* W2  = (const float*)d_in[10];
    const float* g2  = (const float*)d_in[12];
    const float* bt2 = (const float*)d_in[13];
    float* out = (float*)d_out;

    size_t smemA = (size_t)(128 * XPA + 16384) * 4;   // 198656 B
    size_t smem1 = (size_t)(32768 + 16384) * 4;       // 196608 B
    cudaFuncSetAttribute(k_gemmA, cudaFuncAttributeMaxDynamicSharedMemorySize, (int)smemA);
    cudaFuncSetAttribute(k_layer1, cudaFuncAttributeMaxDynamicSharedMemorySize, (int)smem1);

    k_pack<<<72, 256>>>(W0, W1);
    dim3 gA(4, 12);
    k_gemmA<<<gA, 256, smemA>>>(query, support);
    k_mid<<<129, 256>>>(g0, bt0);
    k_layer1<<<GRID1, T1, smem1>>>(g1, bt1, W2, g2, bt2, out);
}